// round 2
// baseline (speedup 1.0000x reference)
#include <cuda_runtime.h>
#include <cuda_bf16.h>

// Blur_by_Kernel: per-batch 21x21 cross-correlation, reflect pad 10.
// out[b,c,y,x] = sum_{i,j} in_reflect[b,c, y+i-10, x+j-10] * ker[b,i,j]
// B=16, C=3, H=W=768, K=21.

#define BDIM 768*0 + 16   // batch (not used as macro really)
static const int H = 768;
static const int W = 768;
static const int KS = 21;
static const int PAD = 10;

// tile geometry
static const int TX = 128;          // output tile width
static const int TY = 32;           // output tile height
static const int SROWS = TY + 20;   // 52 smem rows
static const int SCOLS = TX + 20;   // 148 smem cols (valid)
static const int SW_STRIDE = 150;   // padded row stride (floats, 8B-aligned)

typedef unsigned long long ull;

__device__ __forceinline__ ull pk(float lo, float hi) {
    ull r;
    asm("mov.b64 %0, {%1, %2};" : "=l"(r) : "f"(lo), "f"(hi));
    return r;
}

__device__ __forceinline__ float2 upk(ull v) {
    float2 r;
    asm("mov.b64 {%0, %1}, %2;" : "=f"(r.x), "=f"(r.y) : "l"(v));
    return r;
}

__device__ __forceinline__ void ffma2(ull a, ull b, ull& c) {
    asm("fma.rn.f32x2 %0, %1, %2, %0;" : "+l"(c) : "l"(a), "l"(b));
}

__device__ __forceinline__ int refl(int i, int n) {
    i = (i < 0) ? -i : i;
    if (i >= n) i = 2 * n - 2 - i;
    return i;
}

__global__ __launch_bounds__(256, 2)
void blur_kernel(const float* __restrict__ in,
                 const float* __restrict__ ker,
                 float* __restrict__ out)
{
    __shared__ float  s_in[SROWS * SW_STRIDE];   // 31200 B
    __shared__ float2 s_k2[KS * KS];             //  3528 B (duplicated kernel)

    const int tid   = threadIdx.x;
    const int plane = blockIdx.z;          // b*3 + c
    const int b     = plane / 3;
    const int X0    = blockIdx.x * TX;
    const int Y0    = blockIdx.y * TY;

    // ---- load duplicated kernel for this batch ----
    {
        const float* kb = ker + b * (KS * KS);
        for (int t = tid; t < KS * KS; t += 256) {
            float k = kb[t];
            s_k2[t] = make_float2(k, k);
        }
    }

    // ---- load input tile with reflect padding ----
    {
        const float* pin = in + (long long)plane * H * W;
        const int NLOAD = SROWS * SCOLS;  // 7696
        for (int idx = tid; idx < NLOAD; idx += 256) {
            int ry = idx / SCOLS;
            int rx = idx - ry * SCOLS;
            int gy = refl(Y0 - PAD + ry, H);
            int gx = refl(X0 - PAD + rx, W);
            s_in[ry * SW_STRIDE + rx] = pin[gy * W + gx];
        }
    }
    __syncthreads();

    // ---- compute: each thread -> 8(x) x 2(y) outputs as 4 f32x2 accs x 2 rows ----
    const int tx = tid & 15;      // 0..15  -> x offset tx*8
    const int ty = tid >> 4;      // 0..15  -> y offset ty*2

    ull acc[2][4];
#pragma unroll
    for (int r = 0; r < 2; ++r)
#pragma unroll
        for (int q = 0; q < 4; ++q)
            acc[r][q] = 0ull;

    const int xb = tx * 8;

#pragma unroll 1
    for (int i = 0; i < KS; ++i) {
        const ull* krow = (const ull*)&s_k2[i * KS];
#pragma unroll
        for (int r = 0; r < 2; ++r) {
            const float2* wp =
                (const float2*)&s_in[(ty * 2 + r + i) * SW_STRIDE + xb];
            float2 w2[14];
#pragma unroll
            for (int m = 0; m < 14; ++m) w2[m] = wp[m];

            ull pe[14];   // even pairs (w[2m], w[2m+1])
            ull po[13];   // odd pairs  (w[2m+1], w[2m+2])
#pragma unroll
            for (int m = 0; m < 14; ++m) pe[m] = pk(w2[m].x, w2[m].y);
#pragma unroll
            for (int m = 0; m < 13; ++m) po[m] = pk(w2[m].y, w2[m + 1].x);

#pragma unroll
            for (int j = 0; j < KS; ++j) {
                ull kd = krow[j];
#pragma unroll
                for (int q = 0; q < 4; ++q) {
                    int t = j + 2 * q;
                    ull pair = (t & 1) ? po[t >> 1] : pe[t >> 1];
                    ffma2(pair, kd, acc[r][q]);
                }
            }
        }
    }

    // ---- store ----
    float* pout = out + (long long)plane * H * W;
#pragma unroll
    for (int r = 0; r < 2; ++r) {
        int y = Y0 + ty * 2 + r;
        float2* row = (float2*)&pout[y * W + X0 + xb];
#pragma unroll
        for (int q = 0; q < 4; ++q)
            row[q] = upk(acc[r][q]);
    }
}

extern "C" void kernel_launch(void* const* d_in, const int* in_sizes, int n_in,
                              void* d_out, int out_size)
{
    const float* in  = (const float*)d_in[0];   // (16,3,768,768)
    const float* ker = (const float*)d_in[1];   // (16,21,21)
    float* out = (float*)d_out;

    dim3 grid(W / TX, H / TY, 16 * 3);  // (6, 24, 48)
    dim3 block(256);
    blur_kernel<<<grid, block>>>(in, ker, out);
}

// round 4
// speedup vs baseline: 1.3582x; 1.3582x over previous
#include <cuda_runtime.h>
#include <cuda_bf16.h>

// Blur_by_Kernel: per-batch 21x21 cross-correlation, reflect pad 10.
// out[b,c,y,x] = sum_{i,j} in_reflect[b,c, y+i-10, x+j-10] * ker[b,i,j]
// B=16, C=3, H=W=768, K=21.

static const int H = 768;
static const int W = 768;
static const int KS = 21;
static const int PAD = 10;

static const int TX = 128;          // output tile width
static const int TY = 32;           // output tile height
static const int SROWS = TY + 20;   // 52 smem rows
static const int SCOLS = TX + 20;   // 148 valid smem cols
static const int SSTRIDE = 150;     // padded row stride (floats)
static const int KSTRIDE = 22;      // kernel row stride in float2 (16B-aligned rows)

typedef unsigned long long ull;

// swizzle: XOR bits[3:4] with bits[7:8] of the byte offset.
// Breaks the 4-way conflict of 32B-strided lane accesses while keeping
// 8B alignment. Pure function of address -> apply at store AND load.
__device__ __forceinline__ int swz(int a) { return a ^ ((a >> 4) & 0x18); }

__device__ __forceinline__ void ffma2(ull a, ull b, ull& c) {
    asm("fma.rn.f32x2 %0, %1, %2, %0;" : "+l"(c) : "l"(a), "l"(b));
}

__device__ __forceinline__ ull pk(float lo, float hi) {
    ull r;
    asm("mov.b64 %0, {%1, %2};" : "=l"(r) : "f"(lo), "f"(hi));
    return r;
}

__device__ __forceinline__ float2 upk(ull v) {
    float2 r;
    asm("mov.b64 {%0, %1}, %2;" : "=f"(r.x), "=f"(r.y) : "l"(v));
    return r;
}

__device__ __forceinline__ int refl(int i, int n) {
    i = (i < 0) ? -i : i;
    if (i >= n) i = 2 * n - 2 - i;
    return i;
}

// One kernel-row application: acc[q] += pair(t=j+2q) * k[j], j=0..20.
// Kernel taps fetched 2-at-a-time via LDS.128 broadcast.
__device__ __forceinline__ void apply_row(ull acc[4], const ull pe[14],
                                          const ull po[13], const ull* krow)
{
#pragma unroll
    for (int jj = 0; jj < 10; ++jj) {
        ulonglong2 kd2 = *(const ulonglong2*)(krow + 2 * jj); // taps 2jj, 2jj+1
#pragma unroll
        for (int q = 0; q < 4; ++q) ffma2(pe[jj + q], kd2.x, acc[q]);
#pragma unroll
        for (int q = 0; q < 4; ++q) ffma2(po[jj + q], kd2.y, acc[q]);
    }
    ull kd = krow[20]; // tap j=20 (even)
#pragma unroll
    for (int q = 0; q < 4; ++q) ffma2(pe[10 + q], kd, acc[q]);
}

__global__ __launch_bounds__(256, 2)
void blur_kernel(const float* __restrict__ in,
                 const float* __restrict__ ker,
                 float* __restrict__ out)
{
    __shared__ __align__(128) float  s_in[SROWS * SSTRIDE]; // 31200 B
    __shared__ __align__(16)  float2 s_k2[KS * KSTRIDE];    //  3696 B

    const int tid   = threadIdx.x;
    const int plane = blockIdx.z;          // b*3 + c
    const int b     = plane / 3;
    const int X0    = blockIdx.x * TX;
    const int Y0    = blockIdx.y * TY;

    // ---- duplicated kernel, rows padded to 22 float2 for aligned LDS.128 ----
    {
        const float* kb = ker + b * (KS * KS);
        for (int t = tid; t < KS * KS; t += 256) {
            int i = t / KS, j = t - i * KS;
            float k = kb[t];
            s_k2[i * KSTRIDE + j] = make_float2(k, k);
        }
    }

    // ---- input tile with reflect padding, swizzled store ----
    {
        const float* pin = in + (long long)plane * H * W;
        const int NLOAD = SROWS * SCOLS;  // 7696
        char* sb = (char*)s_in;
        for (int idx = tid; idx < NLOAD; idx += 256) {
            int ry = idx / SCOLS;
            int rx = idx - ry * SCOLS;
            int gy = refl(Y0 - PAD + ry, H);
            int gx = refl(X0 - PAD + rx, W);
            *(float*)(sb + swz((ry * SSTRIDE + rx) * 4)) = pin[gy * W + gx];
        }
    }
    __syncthreads();

    // ---- compute: 8(x) x 2(y) outputs/thread; slide over INPUT rows so each
    //      window is loaded & packed once and feeds both output rows ----
    const int tx = tid & 15;      // x offset tx*8
    const int ty = tid >> 4;      // y offset ty*2
    const int xb = tx * 8;

    ull acc0[4] = {0, 0, 0, 0};
    ull acc1[4] = {0, 0, 0, 0};

    const char* sb = (const char*)s_in;
    int lrow = ((ty * 2) * SSTRIDE + xb) * 4;   // byte offset of window start

#pragma unroll 1
    for (int u = 0; u <= 21; ++u) {
        // load window: 14 aligned float2 (even pairs come free)
        float2 w2[14];
#pragma unroll
        for (int m = 0; m < 14; ++m)
            w2[m] = *(const float2*)(sb + swz(lrow + m * 8));

        ull pe[14];
#pragma unroll
        for (int m = 0; m < 14; ++m) pe[m] = pk(w2[m].x, w2[m].y);
        ull po[13];
#pragma unroll
        for (int m = 0; m < 13; ++m) po[m] = pk(w2[m].y, w2[m + 1].x);

        // input row (ty*2 + u) feeds: r=0 with kernel row u, r=1 with row u-1
        if (u < 21) {
            const ull* krow = (const ull*)((const char*)s_k2 + u * (KSTRIDE * 8));
            apply_row(acc0, pe, po, krow);
        }
        if (u > 0) {
            const ull* krow = (const ull*)((const char*)s_k2 + (u - 1) * (KSTRIDE * 8));
            apply_row(acc1, pe, po, krow);
        }
        lrow += SSTRIDE * 4;
    }

    // ---- store ----
    float* pout = out + (long long)plane * H * W;
    {
        int y0 = Y0 + ty * 2;
        float2* row0 = (float2*)&pout[(long long)y0 * W + X0 + xb];
        float2* row1 = (float2*)&pout[(long long)(y0 + 1) * W + X0 + xb];
#pragma unroll
        for (int q = 0; q < 4; ++q) row0[q] = upk(acc0[q]);
#pragma unroll
        for (int q = 0; q < 4; ++q) row1[q] = upk(acc1[q]);
    }
}

extern "C" void kernel_launch(void* const* d_in, const int* in_sizes, int n_in,
                              void* d_out, int out_size)
{
    const float* in  = (const float*)d_in[0];   // (16,3,768,768)
    const float* ker = (const float*)d_in[1];   // (16,21,21)
    float* out = (float*)d_out;

    dim3 grid(W / TX, H / TY, 16 * 3);  // (6, 24, 48)
    dim3 block(256);
    blur_kernel<<<grid, block>>>(in, ker, out);
}

// round 5
// speedup vs baseline: 1.6011x; 1.1788x over previous
#include <cuda_runtime.h>
#include <cuda_bf16.h>

// Blur_by_Kernel: per-batch 21x21 cross-correlation, reflect pad 10.
// out[b,c,y,x] = sum_{i,j} in_reflect[b,c, y+i-10, x+j-10] * ker[b,i,j]
// B=16, C=3, H=W=768, K=21.
//
// j-paired f32x2 formulation:
//   even out x:  Sum_m pe[q+m] . ke[m],  ke[m] = (k[2m], k[2m+1])   (k[21]=0)
//   odd  out x:  Sum_m pe[q+m] . ko[m],  ko[m] = (k[2m-1], k[2m])   (k[-1]=0)
// where pe[p] = (w[xb+2p], w[xb+2p+1]) are ALIGNED pairs -> no MOV packs.
// Horizontal lo+hi per output at the end.

static const int H = 768;
static const int W = 768;
static const int KS = 21;
static const int PAD = 10;

static const int TX = 128;          // output tile width
static const int TY = 32;           // output tile height
static const int SROWS = TY + 20;   // 52 smem rows
static const int SCOLS = TX + 20;   // 148 valid smem cols
static const int SSTRIDE = 152;     // padded row stride (floats), 608 B (16B mult.)
static const int KROW_F2 = 22;      // kernel row: 11 interleaved (ke, ko) float2
static const int KROW_BYTES = KROW_F2 * 8;   // 176

typedef unsigned long long ull;

// 16B-preserving swizzle: XOR bits[4:5] with bits[7:8].
// Conflict-free LDS.128 for the 32B lane stride used below.
__device__ __forceinline__ int swz2(int a) { return a ^ ((a >> 3) & 0x30); }

__device__ __forceinline__ void ffma2(ull a, ull b, ull& c) {
    asm("fma.rn.f32x2 %0, %1, %2, %0;" : "+l"(c) : "l"(a), "l"(b));
}

__device__ __forceinline__ float2 upk(ull v) {
    float2 r;
    asm("mov.b64 {%0, %1}, %2;" : "=f"(r.x), "=f"(r.y) : "l"(v));
    return r;
}

__device__ __forceinline__ int refl(int i, int n) {
    i = (i < 0) ? -i : i;
    if (i >= n) i = 2 * n - 2 - i;
    return i;
}

__global__ __launch_bounds__(256, 3)
void blur_kernel(const float* __restrict__ in,
                 const float* __restrict__ ker,
                 float* __restrict__ out)
{
    __shared__ __align__(128) float  s_in[SROWS * SSTRIDE]; // 31616 B
    __shared__ __align__(16)  float2 s_kp[KS * KROW_F2];    //  3696 B

    const int tid   = threadIdx.x;
    const int plane = blockIdx.z;          // b*3 + c
    const int b     = plane / 3;
    const int X0    = blockIdx.x * TX;
    const int Y0    = blockIdx.y * TY;

    // ---- kernel pairs: per row i, interleaved ke[m], ko[m] (m=0..10) ----
    {
        const float* kb = ker + b * (KS * KS);
        for (int t = tid; t < KS * 11; t += 256) {
            int i = t / 11, m = t - i * 11;
            const float* kr = kb + i * KS;
            float k2m   = kr[2 * m];
            float k2m1  = (2 * m + 1 < KS) ? kr[2 * m + 1] : 0.0f;
            float k2mm1 = (m > 0) ? kr[2 * m - 1] : 0.0f;
            float2* row = s_kp + i * KROW_F2;
            row[2 * m]     = make_float2(k2m, k2m1);    // ke[m]
            row[2 * m + 1] = make_float2(k2mm1, k2m);   // ko[m]
        }
    }

    // ---- input tile with reflect padding, swizzled store ----
    {
        const float* pin = in + (long long)plane * H * W;
        const int NLOAD = SROWS * SCOLS;  // 7696
        char* sb = (char*)s_in;
        for (int idx = tid; idx < NLOAD; idx += 256) {
            int ry = idx / SCOLS;
            int rx = idx - ry * SCOLS;
            int gy = refl(Y0 - PAD + ry, H);
            int gx = refl(X0 - PAD + rx, W);
            *(float*)(sb + swz2((ry * SSTRIDE + rx) * 4)) = pin[gy * W + gx];
        }
    }
    __syncthreads();

    // ---- compute: 8(x) x 2(y) outputs/thread, slide over INPUT rows ----
    const int tx = tid & 15;      // x offset tx*8
    const int ty = tid >> 4;      // y offset ty*2
    const int xb = tx * 8;

    ull accE0[4] = {0, 0, 0, 0};  // row 0, even outputs
    ull accO0[4] = {0, 0, 0, 0};  // row 0, odd outputs
    ull accE1[4] = {0, 0, 0, 0};  // row 1
    ull accO1[4] = {0, 0, 0, 0};

    const char* sb = (const char*)s_in;
    int lrow = ((ty * 2) * SSTRIDE + xb) * 4;   // byte offset of window start

#pragma unroll 1
    for (int u = 0; u <= 21; ++u) {
        // window: 28 floats = 7 aligned float4 (conflict-free swizzled LDS.128)
        ull pe[14];
#pragma unroll
        for (int t = 0; t < 7; ++t) {
            float4 v = *(const float4*)(sb + swz2(lrow + t * 16));
            pe[2 * t]     = ((const ull*)&v)[0];
            pe[2 * t + 1] = ((const ull*)&v)[1];
        }

        // input row (ty*2+u) feeds: out row 0 with kernel row u, row 1 with u-1
        if (u < 21) {
            const ulonglong2* kr =
                (const ulonglong2*)((const char*)s_kp + u * KROW_BYTES);
#pragma unroll
            for (int m = 0; m < 11; ++m) {
                ulonglong2 kd = kr[m];   // (ke[m], ko[m]) broadcast LDS.128
#pragma unroll
                for (int q = 0; q < 4; ++q) {
                    ffma2(pe[q + m], kd.x, accE0[q]);
                    ffma2(pe[q + m], kd.y, accO0[q]);
                }
            }
        }
        if (u > 0) {
            const ulonglong2* kr =
                (const ulonglong2*)((const char*)s_kp + (u - 1) * KROW_BYTES);
#pragma unroll
            for (int m = 0; m < 11; ++m) {
                ulonglong2 kd = kr[m];
#pragma unroll
                for (int q = 0; q < 4; ++q) {
                    ffma2(pe[q + m], kd.x, accE1[q]);
                    ffma2(pe[q + m], kd.y, accO1[q]);
                }
            }
        }
        lrow += SSTRIDE * 4;
    }

    // ---- horizontal reduce + store ----
    float* pout = out + (long long)plane * H * W;
    {
        int y0 = Y0 + ty * 2;
        float2* row0 = (float2*)&pout[(long long)y0 * W + X0 + xb];
        float2* row1 = (float2*)&pout[(long long)(y0 + 1) * W + X0 + xb];
#pragma unroll
        for (int q = 0; q < 4; ++q) {
            float2 e = upk(accE0[q]), o = upk(accO0[q]);
            row0[q] = make_float2(e.x + e.y, o.x + o.y);
        }
#pragma unroll
        for (int q = 0; q < 4; ++q) {
            float2 e = upk(accE1[q]), o = upk(accO1[q]);
            row1[q] = make_float2(e.x + e.y, o.x + o.y);
        }
    }
}

extern "C" void kernel_launch(void* const* d_in, const int* in_sizes, int n_in,
                              void* d_out, int out_size)
{
    const float* in  = (const float*)d_in[0];   // (16,3,768,768)
    const float* ker = (const float*)d_in[1];   // (16,21,21)
    float* out = (float*)d_out;

    dim3 grid(W / TX, H / TY, 16 * 3);  // (6, 24, 48)
    dim3 block(256);
    blur_kernel<<<grid, block>>>(in, ker, out);
}

// round 6
// speedup vs baseline: 1.8891x; 1.1799x over previous
#include <cuda_runtime.h>
#include <cuda_bf16.h>

// Blur_by_Kernel: per-batch 21x21 cross-correlation, reflect pad 10.
// out[b,c,y,x] = sum_{i,j} in_reflect[b,c, y+i-10, x+j-10] * ker[b,i,j]
// B=16, C=3, H=W=768, K=21.
//
// j-paired f32x2 formulation (no odd-pair MOV packs):
//   even out x=xb+2q:  Sum_m pe[q+m] . ke[m],  ke[m] = (k[2m], k[2m+1]) (k[21]=0)
//   odd  out x=xb+2q+1: Sum_m pe[q+m] . ko[m], ko[m] = (k[2m-1], k[2m]) (k[-1]=0)
// pe[p] = aligned pair (w[xb+2p], w[xb+2p+1]). Horizontal lo+hi at the end.
// Wd=16 outputs/thread: data LDS phases amortize over 2x more FFMA2.

static const int H = 768;
static const int W = 768;
static const int KS = 21;
static const int PAD = 10;

static const int TX = 128;          // output tile width
static const int TY = 64;           // output tile height
static const int SROWS = TY + 20;   // 84 smem rows
static const int SCOLS = TX + 20;   // 148 valid smem cols
static const int SSTRIDE = 152;     // padded row stride (floats), 608 B
static const int KROW_F2 = 22;      // kernel row: 11 interleaved (ke, ko) float2
static const int KROW_BYTES = KROW_F2 * 8;   // 176

static const int SMEM_IN_BYTES = SROWS * SSTRIDE * 4;          // 51072
static const int SMEM_K_OFF    = SMEM_IN_BYTES;                // kernel region
static const int SMEM_TOTAL    = SMEM_IN_BYTES + KS * KROW_BYTES; // 54768

typedef unsigned long long ull;

// 16B-preserving swizzle: XOR bits[4:5] with bits[7:8].
// Conflict-free LDS.128 for the 64B lane stride used below.
__device__ __forceinline__ int swz2(int a) { return a ^ ((a >> 3) & 0x30); }

__device__ __forceinline__ void ffma2(ull a, ull b, ull& c) {
    asm("fma.rn.f32x2 %0, %1, %2, %0;" : "+l"(c) : "l"(a), "l"(b));
}

__device__ __forceinline__ float2 upk(ull v) {
    float2 r;
    asm("mov.b64 {%0, %1}, %2;" : "=f"(r.x), "=f"(r.y) : "l"(v));
    return r;
}

__device__ __forceinline__ int refl(int i, int n) {
    i = (i < 0) ? -i : i;
    if (i >= n) i = 2 * n - 2 - i;
    return i;
}

__global__ __launch_bounds__(256, 2)
void blur_kernel(const float* __restrict__ in,
                 const float* __restrict__ ker,
                 float* __restrict__ out)
{
    extern __shared__ __align__(128) char smem[];
    float*  s_in = (float*)smem;
    float2* s_kp = (float2*)(smem + SMEM_K_OFF);

    const int tid   = threadIdx.x;
    const int plane = blockIdx.z;          // b*3 + c
    const int b     = plane / 3;
    const int X0    = blockIdx.x * TX;
    const int Y0    = blockIdx.y * TY;

    // ---- kernel pairs: per row i, interleaved ke[m], ko[m] (m=0..10) ----
    {
        const float* kb = ker + b * (KS * KS);
        for (int t = tid; t < KS * 11; t += 256) {
            int i = t / 11, m = t - i * 11;
            const float* kr = kb + i * KS;
            float k2m   = kr[2 * m];
            float k2m1  = (2 * m + 1 < KS) ? kr[2 * m + 1] : 0.0f;
            float k2mm1 = (m > 0) ? kr[2 * m - 1] : 0.0f;
            float2* row = s_kp + i * KROW_F2;
            row[2 * m]     = make_float2(k2m, k2m1);    // ke[m]
            row[2 * m + 1] = make_float2(k2mm1, k2m);   // ko[m]
        }
    }

    // ---- input tile with reflect padding, swizzled store ----
    {
        const float* pin = in + (long long)plane * H * W;
        const int NLOAD = SROWS * SCOLS;  // 12432
        char* sb = (char*)s_in;
        for (int idx = tid; idx < NLOAD; idx += 256) {
            int ry = idx / SCOLS;
            int rx = idx - ry * SCOLS;
            int gy = refl(Y0 - PAD + ry, H);
            int gx = refl(X0 - PAD + rx, W);
            *(float*)(sb + swz2((ry * SSTRIDE + rx) * 4)) = pin[gy * W + gx];
        }
    }
    __syncthreads();

    // ---- compute: 16(x) x 2(y) outputs/thread, slide over INPUT rows ----
    const int tx = tid & 7;       // x offset tx*16
    const int ty = tid >> 3;      // y offset ty*2 (0..31)
    const int xb = tx * 16;

    ull accE0[8] = {0, 0, 0, 0, 0, 0, 0, 0};  // row 0, even outputs
    ull accO0[8] = {0, 0, 0, 0, 0, 0, 0, 0};  // row 0, odd outputs
    ull accE1[8] = {0, 0, 0, 0, 0, 0, 0, 0};  // row 1
    ull accO1[8] = {0, 0, 0, 0, 0, 0, 0, 0};

    const char* sb = (const char*)s_in;
    int lrow = ((ty * 2) * SSTRIDE + xb) * 4;   // byte offset of window start

#pragma unroll 1
    for (int u = 0; u <= 21; ++u) {
        // window: 36 floats = 9 aligned float4 (swizzled, conflict-free)
        ull pe[18];
#pragma unroll
        for (int t = 0; t < 9; ++t) {
            float4 v = *(const float4*)(sb + swz2(lrow + t * 16));
            pe[2 * t]     = ((const ull*)&v)[0];
            pe[2 * t + 1] = ((const ull*)&v)[1];
        }

        // input row (ty*2+u) feeds: out row 0 with kernel row u, row 1 with u-1
        if (u < 21) {
            const ulonglong2* kr =
                (const ulonglong2*)((const char*)s_kp + u * KROW_BYTES);
#pragma unroll
            for (int m = 0; m < 11; ++m) {
                ulonglong2 kd = kr[m];   // (ke[m], ko[m]) broadcast LDS.128
#pragma unroll
                for (int q = 0; q < 8; ++q) {
                    ffma2(pe[q + m], kd.x, accE0[q]);
                    ffma2(pe[q + m], kd.y, accO0[q]);
                }
            }
        }
        if (u > 0) {
            const ulonglong2* kr =
                (const ulonglong2*)((const char*)s_kp + (u - 1) * KROW_BYTES);
#pragma unroll
            for (int m = 0; m < 11; ++m) {
                ulonglong2 kd = kr[m];
#pragma unroll
                for (int q = 0; q < 8; ++q) {
                    ffma2(pe[q + m], kd.x, accE1[q]);
                    ffma2(pe[q + m], kd.y, accO1[q]);
                }
            }
        }
        lrow += SSTRIDE * 4;
    }

    // ---- horizontal reduce + store (float4 = 2 even/odd output pairs) ----
    float* pout = out + (long long)plane * H * W;
    {
        int y0 = Y0 + ty * 2;
        float4* row0 = (float4*)&pout[(long long)y0 * W + X0 + xb];
        float4* row1 = (float4*)&pout[(long long)(y0 + 1) * W + X0 + xb];
#pragma unroll
        for (int q2 = 0; q2 < 4; ++q2) {
            float2 e0 = upk(accE0[2 * q2]),     o0 = upk(accO0[2 * q2]);
            float2 e1 = upk(accE0[2 * q2 + 1]), o1 = upk(accO0[2 * q2 + 1]);
            row0[q2] = make_float4(e0.x + e0.y, o0.x + o0.y,
                                   e1.x + e1.y, o1.x + o1.y);
        }
#pragma unroll
        for (int q2 = 0; q2 < 4; ++q2) {
            float2 e0 = upk(accE1[2 * q2]),     o0 = upk(accO1[2 * q2]);
            float2 e1 = upk(accE1[2 * q2 + 1]), o1 = upk(accO1[2 * q2 + 1]);
            row1[q2] = make_float4(e0.x + e0.y, o0.x + o0.y,
                                   e1.x + e1.y, o1.x + o1.y);
        }
    }
}

extern "C" void kernel_launch(void* const* d_in, const int* in_sizes, int n_in,
                              void* d_out, int out_size)
{
    const float* in  = (const float*)d_in[0];   // (16,3,768,768)
    const float* ker = (const float*)d_in[1];   // (16,21,21)
    float* out = (float*)d_out;

    static int smem_set = 0;
    if (!smem_set) {
        cudaFuncSetAttribute(blur_kernel,
                             cudaFuncAttributeMaxDynamicSharedMemorySize,
                             SMEM_TOTAL);
        smem_set = 1;
    }

    dim3 grid(W / TX, H / TY, 16 * 3);  // (6, 12, 48)
    dim3 block(256);
    blur_kernel<<<grid, block, SMEM_TOTAL>>>(in, ker, out);
}